// round 2
// baseline (speedup 1.0000x reference)
#include <cuda_runtime.h>
#include <cuda_bf16.h>
#include <math.h>

// Problem constants (from reference): M = 50000 eval points, N = 1024 gaussians.
#define NG   1024
#define BLK  256

// Scratch for precomputed per-gaussian coefficients (allocation-free rule:
// __device__ globals are the sanctioned scratch mechanism).
//   packA[n] = { A.x, A.y, A.z, C }    A_d = k*inv_var_d,  C = sum_d A_d*q_d^2
//   packB[n] = { B.x, B.y, B.z, I }    B_d = -2*A_d*q_d,   I = intensity
// with k = -0.5 * log2(e), so gauss = exp2( C + sum A_d p_d^2 + sum B_d p_d ).
__device__ float4 g_packA[NG];
__device__ float4 g_packB[NG];

__global__ void pack_gaussians_kernel(const float* __restrict__ positions,
                                      const float* __restrict__ log_scales,
                                      const float* __restrict__ intensities)
{
    int n = blockIdx.x * blockDim.x + threadIdx.x;
    if (n >= NG) return;

    const float k = -0.72134752044448170368f;  // -0.5 * log2(e)
    const float eps = 1e-6f;

    float qx = positions[3 * n + 0];
    float qy = positions[3 * n + 1];
    float qz = positions[3 * n + 2];

    float sx = expf(log_scales[3 * n + 0]);
    float sy = expf(log_scales[3 * n + 1]);
    float sz = expf(log_scales[3 * n + 2]);

    float Ax = k / (sx * sx + eps);
    float Ay = k / (sy * sy + eps);
    float Az = k / (sz * sz + eps);

    float Bx = -2.0f * Ax * qx;
    float By = -2.0f * Ay * qy;
    float Bz = -2.0f * Az * qz;

    float C = Ax * qx * qx + Ay * qy * qy + Az * qz * qz;

    g_packA[n] = make_float4(Ax, Ay, Az, C);
    g_packB[n] = make_float4(Bx, By, Bz, intensities[n]);
}

__global__ __launch_bounds__(BLK, 2)
void eval_gaussians_kernel(const float* __restrict__ points,
                           float* __restrict__ out,
                           int M)
{
    __shared__ float4 sA[NG];
    __shared__ float4 sB[NG];

    // Cooperative stage of all gaussian coefficients into smem (32 KB).
    for (int i = threadIdx.x; i < NG; i += BLK) {
        sA[i] = g_packA[i];
        sB[i] = g_packB[i];
    }
    __syncthreads();

    int m = blockIdx.x * BLK + threadIdx.x;
    int mm = (m < M) ? m : (M - 1);   // keep warp uniform; suppress store below

    float px = points[3 * mm + 0];
    float py = points[3 * mm + 1];
    float pz = points[3 * mm + 2];
    float ppx = px * px;
    float ppy = py * py;
    float ppz = pz * pz;

    // Two accumulators to break the single-FMA dependency chain.
    float acc0 = 0.0f;
    float acc1 = 0.0f;

    #pragma unroll 8
    for (int n = 0; n < NG; n += 2) {
        {
            float4 A = sA[n];
            float4 B = sB[n];
            float e = fmaf(A.x, ppx, A.w);
            e = fmaf(A.y, ppy, e);
            e = fmaf(A.z, ppz, e);
            e = fmaf(B.x, px, e);
            e = fmaf(B.y, py, e);
            e = fmaf(B.z, pz, e);
            float g;
            asm("ex2.approx.ftz.f32 %0, %1;" : "=f"(g) : "f"(e));
            acc0 = fmaf(B.w, g, acc0);
        }
        {
            float4 A = sA[n + 1];
            float4 B = sB[n + 1];
            float e = fmaf(A.x, ppx, A.w);
            e = fmaf(A.y, ppy, e);
            e = fmaf(A.z, ppz, e);
            e = fmaf(B.x, px, e);
            e = fmaf(B.y, py, e);
            e = fmaf(B.z, pz, e);
            float g;
            asm("ex2.approx.ftz.f32 %0, %1;" : "=f"(g) : "f"(e));
            acc1 = fmaf(B.w, g, acc1);
        }
    }

    if (m < M) out[m] = acc0 + acc1;
}

extern "C" void kernel_launch(void* const* d_in, const int* in_sizes, int n_in,
                              void* d_out, int out_size)
{
    const float* points      = (const float*)d_in[0];  // [M,3]
    const float* positions   = (const float*)d_in[1];  // [N,3]
    const float* log_scales  = (const float*)d_in[2];  // [N,3]
    const float* intensities = (const float*)d_in[3];  // [N]
    float* out = (float*)d_out;                        // [M]

    int M = in_sizes[0] / 3;

    pack_gaussians_kernel<<<(NG + BLK - 1) / BLK, BLK>>>(positions, log_scales, intensities);

    int grid = (M + BLK - 1) / BLK;
    eval_gaussians_kernel<<<grid, BLK>>>(points, out, M);
}

// round 6
// speedup vs baseline: 1.3588x; 1.3588x over previous
#include <cuda_runtime.h>
#include <cuda_bf16.h>
#include <math.h>

// M = 50000 eval points, N = 1024 gaussians.
#define NG      1024
#define GPB     128            // gaussians per block (split-N for load balance)
#define NSPLIT  (NG / GPB)     // 8
#define BLK     128            // threads per block
#define PTS     2              // points per thread (packed f32x2 lanes)
#define PPB     (BLK * PTS)    // 256 points per block

typedef unsigned long long u64;

// Prepacked per-gaussian coefficients, every float duplicated into both f32x2
// lanes so the hot loop needs zero lane-packing ops.
//   g_cA2[2n+0] = {AxAx, AyAy}   g_cA2[2n+1] = {AzAz, CC}
//   g_cB2[2n+0] = {BxBx, ByBy}   g_cB2[2n+1] = {BzBz, II}
// with A_d = k*inv_var_d (k = -0.5*log2 e), B_d = -2*A_d*q_d, C = sum A_d q_d^2,
// so gauss = exp2( C + sum A_d p_d^2 + sum B_d p_d ).
__device__ ulonglong2 g_cA2[NG * 2];
__device__ ulonglong2 g_cB2[NG * 2];

__device__ __forceinline__ u64 dupf(float x) {
    u64 d; unsigned u = __float_as_uint(x);
    asm("mov.b64 %0, {%1, %2};" : "=l"(d) : "r"(u), "r"(u));
    return d;
}
__device__ __forceinline__ u64 packf(float lo, float hi) {
    u64 d;
    asm("mov.b64 %0, {%1, %2};" : "=l"(d)
        : "r"(__float_as_uint(lo)), "r"(__float_as_uint(hi)));
    return d;
}
__device__ __forceinline__ void unpackf(u64 v, float& lo, float& hi) {
    unsigned a, b;
    asm("mov.b64 {%0, %1}, %2;" : "=r"(a), "=r"(b) : "l"(v));
    lo = __uint_as_float(a); hi = __uint_as_float(b);
}
__device__ __forceinline__ u64 fma2(u64 a, u64 b, u64 c) {
    u64 d;
    asm("fma.rn.f32x2 %0, %1, %2, %3;" : "=l"(d) : "l"(a), "l"(b), "l"(c));
    return d;
}
__device__ __forceinline__ u64 mul2(u64 a, u64 b) {
    u64 d;
    asm("mul.rn.f32x2 %0, %1, %2;" : "=l"(d) : "l"(a), "l"(b));
    return d;
}
__device__ __forceinline__ float ex2f(float x) {
    float g;
    asm("ex2.approx.ftz.f32 %0, %1;" : "=f"(g) : "f"(x));
    return g;
}

__global__ void zero_out_kernel(float* __restrict__ out, int M) {
    int i = blockIdx.x * blockDim.x + threadIdx.x;
    if (i < M) out[i] = 0.0f;
}

__global__ void pack_gaussians_kernel(const float* __restrict__ positions,
                                      const float* __restrict__ log_scales,
                                      const float* __restrict__ intensities)
{
    int n = blockIdx.x * blockDim.x + threadIdx.x;
    if (n >= NG) return;

    const float k   = -0.72134752044448170368f;  // -0.5 * log2(e)
    const float eps = 1e-6f;

    float qx = positions[3 * n + 0];
    float qy = positions[3 * n + 1];
    float qz = positions[3 * n + 2];

    float sx = expf(log_scales[3 * n + 0]);
    float sy = expf(log_scales[3 * n + 1]);
    float sz = expf(log_scales[3 * n + 2]);

    float Ax = k / (sx * sx + eps);
    float Ay = k / (sy * sy + eps);
    float Az = k / (sz * sz + eps);

    float Bx = -2.0f * Ax * qx;
    float By = -2.0f * Ay * qy;
    float Bz = -2.0f * Az * qz;

    float C = Ax * qx * qx + Ay * qy * qy + Az * qz * qz;

    g_cA2[2 * n + 0] = make_ulonglong2(dupf(Ax), dupf(Ay));
    g_cA2[2 * n + 1] = make_ulonglong2(dupf(Az), dupf(C));
    g_cB2[2 * n + 0] = make_ulonglong2(dupf(Bx), dupf(By));
    g_cB2[2 * n + 1] = make_ulonglong2(dupf(Bz), dupf(intensities[n]));
}

__global__ __launch_bounds__(BLK, 6)
void eval_gaussians_kernel(const float* __restrict__ points,
                           float* __restrict__ out,
                           int M)
{
    __shared__ ulonglong2 sA[GPB * 2];
    __shared__ ulonglong2 sB[GPB * 2];

    // Stage this block's gaussian chunk (8 KB total).
    int gbase = blockIdx.y * GPB;
    const ulonglong2* gA = &g_cA2[gbase * 2];
    const ulonglong2* gB = &g_cB2[gbase * 2];
    for (int i = threadIdx.x; i < GPB * 2; i += BLK) {
        sA[i] = gA[i];
        sB[i] = gB[i];
    }
    __syncthreads();

    int m0 = blockIdx.x * PPB + threadIdx.x;
    int m1 = m0 + BLK;
    int mm0 = min(m0, M - 1);
    int mm1 = min(m1, M - 1);

    float p0x = points[3 * mm0 + 0];
    float p0y = points[3 * mm0 + 1];
    float p0z = points[3 * mm0 + 2];
    float p1x = points[3 * mm1 + 0];
    float p1y = points[3 * mm1 + 1];
    float p1z = points[3 * mm1 + 2];

    u64 Px  = packf(p0x, p1x);
    u64 Py  = packf(p0y, p1y);
    u64 Pz  = packf(p0z, p1z);
    u64 PPx = mul2(Px, Px);
    u64 PPy = mul2(Py, Py);
    u64 PPz = mul2(Pz, Pz);

    u64 acc = 0ull;   // bit pattern of {0.0f, 0.0f}

    #pragma unroll 4
    for (int g = 0; g < GPB; g++) {
        ulonglong2 a01 = sA[2 * g + 0];   // {AxAx, AyAy}
        ulonglong2 a23 = sA[2 * g + 1];   // {AzAz, CC}
        ulonglong2 b01 = sB[2 * g + 0];   // {BxBx, ByBy}
        ulonglong2 b23 = sB[2 * g + 1];   // {BzBz, II}

        u64 e = fma2(a01.x, PPx, a23.y);  // Ax*px^2 + C
        e = fma2(a01.y, PPy, e);
        e = fma2(a23.x, PPz, e);
        e = fma2(b01.x, Px,  e);
        e = fma2(b01.y, Py,  e);
        e = fma2(b23.x, Pz,  e);

        float e0, e1;
        unpackf(e, e0, e1);
        u64 gp = packf(ex2f(e0), ex2f(e1));

        acc = fma2(b23.y, gp, acc);       // += I * gauss (both lanes)
    }

    float a0, a1;
    unpackf(acc, a0, a1);
    if (m0 < M) atomicAdd(&out[m0], a0);
    if (m1 < M) atomicAdd(&out[m1], a1);
}

extern "C" void kernel_launch(void* const* d_in, const int* in_sizes, int n_in,
                              void* d_out, int out_size)
{
    const float* points      = (const float*)d_in[0];  // [M,3]
    const float* positions   = (const float*)d_in[1];  // [N,3]
    const float* log_scales  = (const float*)d_in[2];  // [N,3]
    const float* intensities = (const float*)d_in[3];  // [N]
    float* out = (float*)d_out;                        // [M]

    int M = in_sizes[0] / 3;

    zero_out_kernel<<<(M + 255) / 256, 256>>>(out, M);
    pack_gaussians_kernel<<<(NG + 127) / 128, 128>>>(positions, log_scales, intensities);

    int npb = (M + PPB - 1) / PPB;   // point blocks: 196
    dim3 grid(npb, NSPLIT);          // 196 x 8 = 1568 blocks
    eval_gaussians_kernel<<<grid, BLK>>>(points, out, M);
}

// round 8
// speedup vs baseline: 1.4590x; 1.0738x over previous
#include <cuda_runtime.h>
#include <cuda_bf16.h>
#include <math.h>

// M = 50000 eval points, N = 1024 gaussians.
#define NG      1024
#define GPB     128            // gaussians per block (split-N for load balance)
#define NSPLIT  (NG / GPB)     // 8
#define BLK     128            // threads per block
#define PTS     2              // points per thread (packed f32x2 lanes)
#define PPB     (BLK * PTS)    // 256 points per block

typedef unsigned long long u64;

// Prepacked per-gaussian coefficients, every float duplicated into both f32x2
// lanes so the hot loop needs zero lane-packing ops.
//   g_cA2[2n+0] = {AxAx, AyAy}   g_cA2[2n+1] = {AzAz, CC}
//   g_cB2[2n+0] = {BxBx, ByBy}   g_cB2[2n+1] = {BzBz, II}
// with A_d = k*inv_var_d (k = -0.5*log2 e), B_d = -2*A_d*q_d, C = sum A_d q_d^2,
// so gauss = exp2( C + sum A_d p_d^2 + sum B_d p_d ).
__device__ ulonglong2 g_cA2[NG * 2];
__device__ ulonglong2 g_cB2[NG * 2];

__device__ __forceinline__ u64 dupf(float x) {
    u64 d; unsigned u = __float_as_uint(x);
    asm("mov.b64 %0, {%1, %2};" : "=l"(d) : "r"(u), "r"(u));
    return d;
}
__device__ __forceinline__ u64 packf(float lo, float hi) {
    u64 d;
    asm("mov.b64 %0, {%1, %2};" : "=l"(d)
        : "r"(__float_as_uint(lo)), "r"(__float_as_uint(hi)));
    return d;
}
__device__ __forceinline__ void unpackf(u64 v, float& lo, float& hi) {
    unsigned a, b;
    asm("mov.b64 {%0, %1}, %2;" : "=r"(a), "=r"(b) : "l"(v));
    lo = __uint_as_float(a); hi = __uint_as_float(b);
}
__device__ __forceinline__ u64 fma2(u64 a, u64 b, u64 c) {
    u64 d;
    asm("fma.rn.f32x2 %0, %1, %2, %3;" : "=l"(d) : "l"(a), "l"(b), "l"(c));
    return d;
}
__device__ __forceinline__ u64 mul2(u64 a, u64 b) {
    u64 d;
    asm("mul.rn.f32x2 %0, %1, %2;" : "=l"(d) : "l"(a), "l"(b));
    return d;
}
__device__ __forceinline__ u64 add2(u64 a, u64 b) {
    u64 d;
    asm("add.rn.f32x2 %0, %1, %2;" : "=l"(d) : "l"(a), "l"(b));
    return d;
}
__device__ __forceinline__ float ex2f(float x) {
    float g;
    asm("ex2.approx.ftz.f32 %0, %1;" : "=f"(g) : "f"(x));
    return g;
}

// Fused init kernel: all threads zero the output; the first NG threads also
// compute and store the packed per-gaussian coefficients. One launch instead
// of two (small-launch overhead here is ~4us per kernel).
__global__ void init_kernel(const float* __restrict__ positions,
                            const float* __restrict__ log_scales,
                            const float* __restrict__ intensities,
                            float* __restrict__ out, int M)
{
    int i = blockIdx.x * blockDim.x + threadIdx.x;
    if (i < M) out[i] = 0.0f;

    if (i < NG) {
        const float k   = -0.72134752044448170368f;  // -0.5 * log2(e)
        const float eps = 1e-6f;

        float qx = positions[3 * i + 0];
        float qy = positions[3 * i + 1];
        float qz = positions[3 * i + 2];

        float sx = expf(log_scales[3 * i + 0]);
        float sy = expf(log_scales[3 * i + 1]);
        float sz = expf(log_scales[3 * i + 2]);

        float Ax = k / (sx * sx + eps);
        float Ay = k / (sy * sy + eps);
        float Az = k / (sz * sz + eps);

        float Bx = -2.0f * Ax * qx;
        float By = -2.0f * Ay * qy;
        float Bz = -2.0f * Az * qz;

        float C = Ax * qx * qx + Ay * qy * qy + Az * qz * qz;

        g_cA2[2 * i + 0] = make_ulonglong2(dupf(Ax), dupf(Ay));
        g_cA2[2 * i + 1] = make_ulonglong2(dupf(Az), dupf(C));
        g_cB2[2 * i + 0] = make_ulonglong2(dupf(Bx), dupf(By));
        g_cB2[2 * i + 1] = make_ulonglong2(dupf(Bz), dupf(intensities[i]));
    }
}

__global__ __launch_bounds__(BLK, 6)
void eval_gaussians_kernel(const float* __restrict__ points,
                           float* __restrict__ out,
                           int M)
{
    __shared__ ulonglong2 sA[GPB * 2];
    __shared__ ulonglong2 sB[GPB * 2];

    // Stage this block's gaussian chunk (8 KB total).
    int gbase = blockIdx.y * GPB;
    const ulonglong2* gA = &g_cA2[gbase * 2];
    const ulonglong2* gB = &g_cB2[gbase * 2];
    for (int i = threadIdx.x; i < GPB * 2; i += BLK) {
        sA[i] = gA[i];
        sB[i] = gB[i];
    }
    __syncthreads();

    int m0 = blockIdx.x * PPB + threadIdx.x;
    int m1 = m0 + BLK;
    int mm0 = min(m0, M - 1);
    int mm1 = min(m1, M - 1);

    float p0x = points[3 * mm0 + 0];
    float p0y = points[3 * mm0 + 1];
    float p0z = points[3 * mm0 + 2];
    float p1x = points[3 * mm1 + 0];
    float p1y = points[3 * mm1 + 1];
    float p1z = points[3 * mm1 + 2];

    u64 Px  = packf(p0x, p1x);
    u64 Py  = packf(p0y, p1y);
    u64 Pz  = packf(p0z, p1z);
    u64 PPx = mul2(Px, Px);
    u64 PPy = mul2(Py, Py);
    u64 PPz = mul2(Pz, Pz);

    u64 acc = 0ull;   // bit pattern of {0.0f, 0.0f}

    #pragma unroll 8
    for (int g = 0; g < GPB; g++) {
        ulonglong2 a01 = sA[2 * g + 0];   // {AxAx, AyAy}
        ulonglong2 a23 = sA[2 * g + 1];   // {AzAz, CC}
        ulonglong2 b01 = sB[2 * g + 0];   // {BxBx, ByBy}
        ulonglong2 b23 = sB[2 * g + 1];   // {BzBz, II}

        // Split the exponent into two independent 3-deep chains to cut the
        // dependent-FMA latency from ~24 to ~13 cycles.
        u64 u = fma2(a01.x, PPx, a23.y);  // Ax*px^2 + C
        u64 v = mul2(a01.y, PPy);         // Ay*py^2
        u = fma2(b01.x, Px, u);           // + Bx*px
        v = fma2(a23.x, PPz, v);          // + Az*pz^2
        u = fma2(b01.y, Py, u);           // + By*py
        v = fma2(b23.x, Pz, v);           // + Bz*pz
        u64 e = add2(u, v);

        float e0, e1;
        unpackf(e, e0, e1);
        u64 gp = packf(ex2f(e0), ex2f(e1));

        acc = fma2(b23.y, gp, acc);       // += I * gauss (both lanes)
    }

    float a0, a1;
    unpackf(acc, a0, a1);
    if (m0 < M) atomicAdd(&out[m0], a0);
    if (m1 < M) atomicAdd(&out[m1], a1);
}

extern "C" void kernel_launch(void* const* d_in, const int* in_sizes, int n_in,
                              void* d_out, int out_size)
{
    const float* points      = (const float*)d_in[0];  // [M,3]
    const float* positions   = (const float*)d_in[1];  // [N,3]
    const float* log_scales  = (const float*)d_in[2];  // [N,3]
    const float* intensities = (const float*)d_in[3];  // [N]
    float* out = (float*)d_out;                        // [M]

    int M = in_sizes[0] / 3;

    // One fused init launch: zero out[] + pack gaussian coefficients.
    init_kernel<<<(M + 255) / 256, 256>>>(positions, log_scales, intensities, out, M);

    int npb = (M + PPB - 1) / PPB;   // point blocks: 196
    dim3 grid(npb, NSPLIT);          // 196 x 8 = 1568 blocks
    eval_gaussians_kernel<<<grid, BLK>>>(points, out, M);
}

// round 9
// speedup vs baseline: 1.7980x; 1.2323x over previous
#include <cuda_runtime.h>
#include <cuda_bf16.h>
#include <math.h>

// M = 50000 eval points, N = 1024 gaussians.
#define NG      1024
#define GPB     64             // gaussians per block (split-N for load balance)
#define NSPLIT  (NG / GPB)     // 16
#define BLK     128            // threads per block
#define PTS     4              // points per thread (2 packed f32x2 pairs)
#define PPB     (BLK * PTS)    // 512 points per block

typedef unsigned long long u64;

// Prepacked per-gaussian coefficients, every float duplicated into both f32x2
// lanes so the hot loop needs zero lane-packing ops.
//   g_cA2[2n+0] = {AxAx, AyAy}   g_cA2[2n+1] = {AzAz, CC}
//   g_cB2[2n+0] = {BxBx, ByBy}   g_cB2[2n+1] = {BzBz, II}
// with A_d = k*inv_var_d (k = -0.5*log2 e), B_d = -2*A_d*q_d, C = sum A_d q_d^2,
// so gauss = exp2( C + sum A_d p_d^2 + sum B_d p_d ).
__device__ ulonglong2 g_cA2[NG * 2];
__device__ ulonglong2 g_cB2[NG * 2];

__device__ __forceinline__ u64 dupf(float x) {
    u64 d; unsigned u = __float_as_uint(x);
    asm("mov.b64 %0, {%1, %2};" : "=l"(d) : "r"(u), "r"(u));
    return d;
}
__device__ __forceinline__ u64 packf(float lo, float hi) {
    u64 d;
    asm("mov.b64 %0, {%1, %2};" : "=l"(d)
        : "r"(__float_as_uint(lo)), "r"(__float_as_uint(hi)));
    return d;
}
__device__ __forceinline__ void unpackf(u64 v, float& lo, float& hi) {
    unsigned a, b;
    asm("mov.b64 {%0, %1}, %2;" : "=r"(a), "=r"(b) : "l"(v));
    lo = __uint_as_float(a); hi = __uint_as_float(b);
}
__device__ __forceinline__ u64 fma2(u64 a, u64 b, u64 c) {
    u64 d;
    asm("fma.rn.f32x2 %0, %1, %2, %3;" : "=l"(d) : "l"(a), "l"(b), "l"(c));
    return d;
}
__device__ __forceinline__ u64 mul2(u64 a, u64 b) {
    u64 d;
    asm("mul.rn.f32x2 %0, %1, %2;" : "=l"(d) : "l"(a), "l"(b));
    return d;
}
__device__ __forceinline__ u64 add2(u64 a, u64 b) {
    u64 d;
    asm("add.rn.f32x2 %0, %1, %2;" : "=l"(d) : "l"(a), "l"(b));
    return d;
}
__device__ __forceinline__ float ex2f(float x) {
    float g;
    asm("ex2.approx.ftz.f32 %0, %1;" : "=f"(g) : "f"(x));
    return g;
}

// Fused init kernel: all threads zero the output; the first NG threads also
// compute and store the packed per-gaussian coefficients.
__global__ void init_kernel(const float* __restrict__ positions,
                            const float* __restrict__ log_scales,
                            const float* __restrict__ intensities,
                            float* __restrict__ out, int M)
{
    int i = blockIdx.x * blockDim.x + threadIdx.x;
    if (i < M) out[i] = 0.0f;

    if (i < NG) {
        const float k   = -0.72134752044448170368f;  // -0.5 * log2(e)
        const float eps = 1e-6f;

        float qx = positions[3 * i + 0];
        float qy = positions[3 * i + 1];
        float qz = positions[3 * i + 2];

        float sx = expf(log_scales[3 * i + 0]);
        float sy = expf(log_scales[3 * i + 1]);
        float sz = expf(log_scales[3 * i + 2]);

        float Ax = k / (sx * sx + eps);
        float Ay = k / (sy * sy + eps);
        float Az = k / (sz * sz + eps);

        float Bx = -2.0f * Ax * qx;
        float By = -2.0f * Ay * qy;
        float Bz = -2.0f * Az * qz;

        float C = Ax * qx * qx + Ay * qy * qy + Az * qz * qz;

        g_cA2[2 * i + 0] = make_ulonglong2(dupf(Ax), dupf(Ay));
        g_cA2[2 * i + 1] = make_ulonglong2(dupf(Az), dupf(C));
        g_cB2[2 * i + 0] = make_ulonglong2(dupf(Bx), dupf(By));
        g_cB2[2 * i + 1] = make_ulonglong2(dupf(Bz), dupf(intensities[i]));
    }
}

__global__ __launch_bounds__(BLK, 6)
void eval_gaussians_kernel(const float* __restrict__ points,
                           float* __restrict__ out,
                           int M)
{
    __shared__ ulonglong2 sA[GPB * 2];
    __shared__ ulonglong2 sB[GPB * 2];

    // Stage this block's gaussian chunk (4 KB total).
    int gbase = blockIdx.y * GPB;
    const ulonglong2* gA = &g_cA2[gbase * 2];
    const ulonglong2* gB = &g_cB2[gbase * 2];
    for (int i = threadIdx.x; i < GPB * 2; i += BLK) {
        sA[i] = gA[i];
        sB[i] = gB[i];
    }
    __syncthreads();

    // 4 points per thread: two independent f32x2 pairs (q = pair index).
    int mbase = blockIdx.x * PPB + threadIdx.x;
    int m0 = mbase;            // pair 0 lanes: m0, m0+BLK
    int m1 = mbase + BLK;
    int m2 = mbase + 2 * BLK;  // pair 1 lanes: m2, m2+BLK
    int m3 = mbase + 3 * BLK;
    int mm0 = min(m0, M - 1), mm1 = min(m1, M - 1);
    int mm2 = min(m2, M - 1), mm3 = min(m3, M - 1);

    float p0x = points[3 * mm0 + 0], p0y = points[3 * mm0 + 1], p0z = points[3 * mm0 + 2];
    float p1x = points[3 * mm1 + 0], p1y = points[3 * mm1 + 1], p1z = points[3 * mm1 + 2];
    float p2x = points[3 * mm2 + 0], p2y = points[3 * mm2 + 1], p2z = points[3 * mm2 + 2];
    float p3x = points[3 * mm3 + 0], p3y = points[3 * mm3 + 1], p3z = points[3 * mm3 + 2];

    u64 Pax  = packf(p0x, p1x), Pay = packf(p0y, p1y), Paz = packf(p0z, p1z);
    u64 Pbx  = packf(p2x, p3x), Pby = packf(p2y, p3y), Pbz = packf(p2z, p3z);
    u64 PPax = mul2(Pax, Pax), PPay = mul2(Pay, Pay), PPaz = mul2(Paz, Paz);
    u64 PPbx = mul2(Pbx, Pbx), PPby = mul2(Pby, Pby), PPbz = mul2(Pbz, Pbz);

    u64 accA = 0ull;   // {0.0f, 0.0f}
    u64 accB = 0ull;

    #pragma unroll 4
    for (int g = 0; g < GPB; g++) {
        ulonglong2 a01 = sA[2 * g + 0];   // {AxAx, AyAy}
        ulonglong2 a23 = sA[2 * g + 1];   // {AzAz, CC}
        ulonglong2 b01 = sB[2 * g + 0];   // {BxBx, ByBy}
        ulonglong2 b23 = sB[2 * g + 1];   // {BzBz, II}

        // Pair A: two independent 3-deep chains.
        u64 uA = fma2(a01.x, PPax, a23.y);
        u64 vA = mul2(a01.y, PPay);
        // Pair B: same, fully independent.
        u64 uB = fma2(a01.x, PPbx, a23.y);
        u64 vB = mul2(a01.y, PPby);

        uA = fma2(b01.x, Pax, uA);
        vA = fma2(a23.x, PPaz, vA);
        uB = fma2(b01.x, Pbx, uB);
        vB = fma2(a23.x, PPbz, vB);

        uA = fma2(b01.y, Pay, uA);
        vA = fma2(b23.x, Paz, vA);
        uB = fma2(b01.y, Pby, uB);
        vB = fma2(b23.x, Pbz, vB);

        u64 eA = add2(uA, vA);
        u64 eB = add2(uB, vB);

        float eA0, eA1, eB0, eB1;
        unpackf(eA, eA0, eA1);
        unpackf(eB, eB0, eB1);
        u64 gpA = packf(ex2f(eA0), ex2f(eA1));
        u64 gpB = packf(ex2f(eB0), ex2f(eB1));

        accA = fma2(b23.y, gpA, accA);    // += I * gauss
        accB = fma2(b23.y, gpB, accB);
    }

    float a0, a1, a2, a3;
    unpackf(accA, a0, a1);
    unpackf(accB, a2, a3);
    if (m0 < M) atomicAdd(&out[m0], a0);
    if (m1 < M) atomicAdd(&out[m1], a1);
    if (m2 < M) atomicAdd(&out[m2], a2);
    if (m3 < M) atomicAdd(&out[m3], a3);
}

extern "C" void kernel_launch(void* const* d_in, const int* in_sizes, int n_in,
                              void* d_out, int out_size)
{
    const float* points      = (const float*)d_in[0];  // [M,3]
    const float* positions   = (const float*)d_in[1];  // [N,3]
    const float* log_scales  = (const float*)d_in[2];  // [N,3]
    const float* intensities = (const float*)d_in[3];  // [N]
    float* out = (float*)d_out;                        // [M]

    int M = in_sizes[0] / 3;

    // One fused init launch: zero out[] + pack gaussian coefficients.
    init_kernel<<<(M + 255) / 256, 256>>>(positions, log_scales, intensities, out, M);

    int npb = (M + PPB - 1) / PPB;   // point blocks: 98
    dim3 grid(npb, NSPLIT);          // 98 x 16 = 1568 blocks
    eval_gaussians_kernel<<<grid, BLK>>>(points, out, M);
}

// round 10
// speedup vs baseline: 1.8494x; 1.0286x over previous
#include <cuda_runtime.h>
#include <cuda_bf16.h>
#include <math.h>

// M = 50000 eval points, N = 1024 gaussians.
#define NG      1024
#define GPB     64             // gaussians per block (split-N for load balance)
#define NSPLIT  (NG / GPB)     // 16
#define BLK     128            // threads per block
#define PTS     4              // points per thread (2 packed f32x2 pairs)
#define PPB     (BLK * PTS)    // 512 points per block

typedef unsigned long long u64;

// Prepacked per-gaussian coefficients, every float duplicated into both f32x2
// lanes so the hot loop needs zero lane-packing ops.
//   g_cA2[2n+0] = {AxAx, AyAy}   g_cA2[2n+1] = {AzAz, CC}
//   g_cB2[2n+0] = {BxBx, ByBy}   g_cB2[2n+1] = {BzBz, II}
// with A_d = k*inv_var_d (k = -0.5*log2 e), B_d = -2*A_d*q_d, C = sum A_d q_d^2,
// so gauss = exp2( C + sum A_d p_d^2 + sum B_d p_d ).
__device__ ulonglong2 g_cA2[NG * 2];
__device__ ulonglong2 g_cB2[NG * 2];

__device__ __forceinline__ u64 dupf(float x) {
    u64 d; unsigned u = __float_as_uint(x);
    asm("mov.b64 %0, {%1, %2};" : "=l"(d) : "r"(u), "r"(u));
    return d;
}
__device__ __forceinline__ u64 packf(float lo, float hi) {
    u64 d;
    asm("mov.b64 %0, {%1, %2};" : "=l"(d)
        : "r"(__float_as_uint(lo)), "r"(__float_as_uint(hi)));
    return d;
}
__device__ __forceinline__ void unpackf(u64 v, float& lo, float& hi) {
    unsigned a, b;
    asm("mov.b64 {%0, %1}, %2;" : "=r"(a), "=r"(b) : "l"(v));
    lo = __uint_as_float(a); hi = __uint_as_float(b);
}
__device__ __forceinline__ u64 fma2(u64 a, u64 b, u64 c) {
    u64 d;
    asm("fma.rn.f32x2 %0, %1, %2, %3;" : "=l"(d) : "l"(a), "l"(b), "l"(c));
    return d;
}
__device__ __forceinline__ u64 mul2(u64 a, u64 b) {
    u64 d;
    asm("mul.rn.f32x2 %0, %1, %2;" : "=l"(d) : "l"(a), "l"(b));
    return d;
}
__device__ __forceinline__ float ex2f(float x) {
    float g;
    asm("ex2.approx.ftz.f32 %0, %1;" : "=f"(g) : "f"(x));
    return g;
}

// Fused init kernel: all threads zero the output; the first NG threads also
// compute and store the packed per-gaussian coefficients.
__global__ void init_kernel(const float* __restrict__ positions,
                            const float* __restrict__ log_scales,
                            const float* __restrict__ intensities,
                            float* __restrict__ out, int M)
{
    int i = blockIdx.x * blockDim.x + threadIdx.x;
    if (i < M) out[i] = 0.0f;

    if (i < NG) {
        const float k   = -0.72134752044448170368f;  // -0.5 * log2(e)
        const float eps = 1e-6f;

        float qx = positions[3 * i + 0];
        float qy = positions[3 * i + 1];
        float qz = positions[3 * i + 2];

        float sx = expf(log_scales[3 * i + 0]);
        float sy = expf(log_scales[3 * i + 1]);
        float sz = expf(log_scales[3 * i + 2]);

        float Ax = k / (sx * sx + eps);
        float Ay = k / (sy * sy + eps);
        float Az = k / (sz * sz + eps);

        float Bx = -2.0f * Ax * qx;
        float By = -2.0f * Ay * qy;
        float Bz = -2.0f * Az * qz;

        float C = Ax * qx * qx + Ay * qy * qy + Az * qz * qz;

        g_cA2[2 * i + 0] = make_ulonglong2(dupf(Ax), dupf(Ay));
        g_cA2[2 * i + 1] = make_ulonglong2(dupf(Az), dupf(C));
        g_cB2[2 * i + 0] = make_ulonglong2(dupf(Bx), dupf(By));
        g_cB2[2 * i + 1] = make_ulonglong2(dupf(Bz), dupf(intensities[i]));
    }
}

__global__ __launch_bounds__(BLK, 8)
void eval_gaussians_kernel(const float* __restrict__ points,
                           float* __restrict__ out,
                           int M)
{
    __shared__ ulonglong2 sA[GPB * 2];
    __shared__ ulonglong2 sB[GPB * 2];

    // Stage this block's gaussian chunk (4 KB total).
    int gbase = blockIdx.y * GPB;
    const ulonglong2* gA = &g_cA2[gbase * 2];
    const ulonglong2* gB = &g_cB2[gbase * 2];
    for (int i = threadIdx.x; i < GPB * 2; i += BLK) {
        sA[i] = gA[i];
        sB[i] = gB[i];
    }
    __syncthreads();

    // 4 points per thread: two independent f32x2 pairs.
    int mbase = blockIdx.x * PPB + threadIdx.x;
    int m0 = mbase;            // pair A lanes: m0, m1
    int m1 = mbase + BLK;
    int m2 = mbase + 2 * BLK;  // pair B lanes: m2, m3
    int m3 = mbase + 3 * BLK;
    int mm0 = min(m0, M - 1), mm1 = min(m1, M - 1);
    int mm2 = min(m2, M - 1), mm3 = min(m3, M - 1);

    float p0x = points[3 * mm0 + 0], p0y = points[3 * mm0 + 1], p0z = points[3 * mm0 + 2];
    float p1x = points[3 * mm1 + 0], p1y = points[3 * mm1 + 1], p1z = points[3 * mm1 + 2];
    float p2x = points[3 * mm2 + 0], p2y = points[3 * mm2 + 1], p2z = points[3 * mm2 + 2];
    float p3x = points[3 * mm3 + 0], p3y = points[3 * mm3 + 1], p3z = points[3 * mm3 + 2];

    u64 Pax  = packf(p0x, p1x), Pay = packf(p0y, p1y), Paz = packf(p0z, p1z);
    u64 Pbx  = packf(p2x, p3x), Pby = packf(p2y, p3y), Pbz = packf(p2z, p3z);
    u64 PPax = mul2(Pax, Pax), PPay = mul2(Pay, Pay), PPaz = mul2(Paz, Paz);
    u64 PPbx = mul2(Pbx, Pbx), PPby = mul2(Pby, Pby), PPbz = mul2(Pbz, Pbz);

    u64 accA = 0ull;   // {0.0f, 0.0f}
    u64 accB = 0ull;

    #pragma unroll 4
    for (int g = 0; g < GPB; g++) {
        ulonglong2 a01 = sA[2 * g + 0];   // {AxAx, AyAy}
        ulonglong2 a23 = sA[2 * g + 1];   // {AzAz, CC}
        ulonglong2 b01 = sB[2 * g + 0];   // {BxBx, ByBy}
        ulonglong2 b23 = sB[2 * g + 1];   // {BzBz, II}

        // Single 6-deep FMA chain per pair (min op count); the two pairs are
        // independent, and 8 warps/SMSP cover the chain latency.
        u64 eA = fma2(a01.x, PPax, a23.y);
        u64 eB = fma2(a01.x, PPbx, a23.y);
        eA = fma2(a01.y, PPay, eA);
        eB = fma2(a01.y, PPby, eB);
        eA = fma2(a23.x, PPaz, eA);
        eB = fma2(a23.x, PPbz, eB);
        eA = fma2(b01.x, Pax, eA);
        eB = fma2(b01.x, Pbx, eB);
        eA = fma2(b01.y, Pay, eA);
        eB = fma2(b01.y, Pby, eB);
        eA = fma2(b23.x, Paz, eA);
        eB = fma2(b23.x, Pbz, eB);

        float eA0, eA1, eB0, eB1;
        unpackf(eA, eA0, eA1);
        unpackf(eB, eB0, eB1);
        u64 gpA = packf(ex2f(eA0), ex2f(eA1));
        u64 gpB = packf(ex2f(eB0), ex2f(eB1));

        accA = fma2(b23.y, gpA, accA);    // += I * gauss
        accB = fma2(b23.y, gpB, accB);
    }

    float a0, a1, a2, a3;
    unpackf(accA, a0, a1);
    unpackf(accB, a2, a3);
    if (m0 < M) atomicAdd(&out[m0], a0);
    if (m1 < M) atomicAdd(&out[m1], a1);
    if (m2 < M) atomicAdd(&out[m2], a2);
    if (m3 < M) atomicAdd(&out[m3], a3);
}

extern "C" void kernel_launch(void* const* d_in, const int* in_sizes, int n_in,
                              void* d_out, int out_size)
{
    const float* points      = (const float*)d_in[0];  // [M,3]
    const float* positions   = (const float*)d_in[1];  // [N,3]
    const float* log_scales  = (const float*)d_in[2];  // [N,3]
    const float* intensities = (const float*)d_in[3];  // [N]
    float* out = (float*)d_out;                        // [M]

    int M = in_sizes[0] / 3;

    // One fused init launch: zero out[] + pack gaussian coefficients.
    init_kernel<<<(M + 255) / 256, 256>>>(positions, log_scales, intensities, out, M);

    int npb = (M + PPB - 1) / PPB;   // point blocks: 98
    dim3 grid(npb, NSPLIT);          // 98 x 16 = 1568 blocks
    eval_gaussians_kernel<<<grid, BLK>>>(points, out, M);
}